// round 6
// baseline (speedup 1.0000x reference)
#include <cuda_runtime.h>
#include <math.h>

#define NPTS    4096
#define NTOT    8192
#define NPROJ   2000
#define NTHREADS 1024
#define PER_TH  8          // NTOT / NTHREADS
#define HBINS   8193       // levels -4096..4096

// per-projection W1 results (device scratch; no allocation)
__device__ float g_w1[NPROJ];

// ---------------------------------------------------------------------------
// block-wide exclusive scan helpers (1024 threads = 32 warps)
// ---------------------------------------------------------------------------
__device__ __forceinline__ int blockScanExclInt(int v, int* scr, int tid) {
    int lane = tid & 31, w = tid >> 5;
    int inc = v;
#pragma unroll
    for (int o = 1; o < 32; o <<= 1) {
        int y = __shfl_up_sync(0xffffffffu, inc, o);
        if (lane >= o) inc += y;
    }
    if (lane == 31) scr[w] = inc;
    __syncthreads();
    if (w == 0) {
        int t = scr[lane];
#pragma unroll
        for (int o = 1; o < 32; o <<= 1) {
            int y = __shfl_up_sync(0xffffffffu, t, o);
            if (lane >= o) t += y;
        }
        scr[lane] = t;
    }
    __syncthreads();
    int base = (w == 0) ? 0 : scr[w - 1];
    return base + (inc - v);
}

__device__ __forceinline__ float blockScanExclF(float v, float* scr, int tid) {
    int lane = tid & 31, w = tid >> 5;
    float inc = v;
#pragma unroll
    for (int o = 1; o < 32; o <<= 1) {
        float y = __shfl_up_sync(0xffffffffu, inc, o);
        if (lane >= o) inc += y;
    }
    if (lane == 31) scr[w] = inc;
    __syncthreads();
    if (w == 0) {
        float t = scr[lane];
#pragma unroll
        for (int o = 1; o < 32; o <<= 1) {
            float y = __shfl_up_sync(0xffffffffu, t, o);
            if (lane >= o) t += y;
        }
        scr[lane] = t;
    }
    __syncthreads();
    float base = (w == 0) ? 0.f : scr[w - 1];
    return base + (inc - v);
}

// ---------------------------------------------------------------------------
// main kernel: one CTA per projection
// ---------------------------------------------------------------------------
__global__ __launch_bounds__(NTHREADS)
void swd_proj_kernel(const float* __restrict__ Xs,
                     const float* __restrict__ Xt,
                     const float* __restrict__ Us)
{
    extern __shared__ unsigned smem_u[];
    unsigned* keys = smem_u;                         // [0, 8192)
    float*    hist = (float*)&smem_u[NTOT];          // [8192, 8192+8193)
    float*    fscr = (float*)&smem_u[NTOT + HBINS];  // 32 floats scan scratch
    int*      iscr = (int*)&smem_u[NTOT + HBINS + 40];

    const int tid = threadIdx.x;
    const int p   = blockIdx.x;

    // projection basis: Us[p, d, k], row-major -> Us[p*6 + d*2 + k]
    const float u00 = Us[p * 6 + 0], u01 = Us[p * 6 + 1];
    const float u10 = Us[p * 6 + 2], u11 = Us[p * 6 + 3];
    const float u20 = Us[p * 6 + 4], u21 = Us[p * 6 + 5];

    const float PIF    = 3.14159265358979323846f;
    const float INV2PI = 0.15915494309189535f;

    // ---- compute packed angle keys: (float_bits << 1) | tag ----------------
    for (int i = tid; i < NPTS; i += NTHREADS) {
        float x0 = Xs[3 * i], x1 = Xs[3 * i + 1], x2 = Xs[3 * i + 2];
        float px = x0 * u00 + x1 * u10 + x2 * u20;
        float py = x0 * u01 + x1 * u11 + x2 * u21;
        float ang = (atan2f(-py, -px) + PIF) * INV2PI;   // in [0, 1]
        keys[i] = (__float_as_uint(ang) << 1);           // tag 0 = u
    }
    for (int i = tid; i < NPTS; i += NTHREADS) {
        float x0 = Xt[3 * i], x1 = Xt[3 * i + 1], x2 = Xt[3 * i + 2];
        float px = x0 * u00 + x1 * u10 + x2 * u20;
        float py = x0 * u01 + x1 * u11 + x2 * u21;
        float ang = (atan2f(-py, -px) + PIF) * INV2PI;
        keys[NPTS + i] = (__float_as_uint(ang) << 1) | 1u;  // tag 1 = v
    }

    // thread 0 seeds fallback level (unreachable in practice)
    if (tid == 0) iscr[0] = -NPTS;

    // ---- bitonic sort of 8192 uint32 keys in smem --------------------------
    for (unsigned k = 2; k <= NTOT; k <<= 1) {
        for (unsigned j = k >> 1; j > 0; j >>= 1) {
            __syncthreads();
#pragma unroll
            for (int e = 0; e < (NTOT / 2) / NTHREADS; ++e) {
                unsigned c = (unsigned)tid + (unsigned)e * NTHREADS;  // CE id
                unsigned a = ((c & ~(j - 1u)) << 1) | (c & (j - 1u));
                unsigned b = a | j;
                unsigned x = keys[a], y = keys[b];
                bool up = ((a & k) == 0u);
                if ((x > y) == up) { keys[a] = y; keys[b] = x; }
            }
        }
    }
    __syncthreads();

    // ---- per-thread chunk of 8 sorted elements ------------------------------
    const int base = tid * PER_TH;
    unsigned mykeys[PER_TH];
    int vcnt = 0;
#pragma unroll
    for (int e = 0; e < PER_TH; ++e) {
        mykeys[e] = keys[base + e];
        vcnt += (int)(mykeys[e] & 1u);
    }

    // zero histogram while scan runs
    for (int i = tid; i < HBINS; i += NTHREADS) hist[i] = 0.f;

    int vexcl = blockScanExclInt(vcnt, iscr + 4, tid);   // #v before this chunk
    __syncthreads();                                     // hist zero + scan done

    // ---- fill histogram of levels weighted by deltas ------------------------
    int   levs[PER_TH];
    float dels[PER_TH];
    {
        int vrun = vexcl;
        float vnext_last = (tid == NTHREADS - 1) ? 1.0f
                           : __uint_as_float(keys[base + PER_TH] >> 1);
#pragma unroll
        for (int e = 0; e < PER_TH; ++e) {
            int gi = base + e;
            vrun += (int)(mykeys[e] & 1u);
            int lev = (gi + 1) - 2 * vrun;               // cdf_int in [-4096,4096]
            float vcur  = __uint_as_float(mykeys[e] >> 1);
            float vnext = (e < PER_TH - 1)
                          ? __uint_as_float(mykeys[e + 1] >> 1)
                          : vnext_last;
            float delta = vnext - vcur;
            levs[e] = lev;
            dels[e] = delta;
            atomicAdd(&hist[lev + NPTS], delta);
        }
    }
    __syncthreads();

    // ---- weighted median of levels: first bin where cum weight >= 0.5 ------
    {
        // thread t owns bins [8t, 8t+8); thread 1023 also owns bin 8192
        int nb = (tid == NTHREADS - 1) ? 9 : 8;
        int b0 = tid * 8;
        float s = 0.f;
        for (int e = 0; e < nb; ++e) s += hist[b0 + e];
        float excl = blockScanExclF(s, fscr, tid);
        if (excl < 0.5f && excl + s >= 0.5f) {
            float run = excl;
            int levm = b0 + nb - 1 - NPTS;   // robust default within chunk
            for (int e = 0; e < nb; ++e) {
                run += hist[b0 + e];
                if (run >= 0.5f) { levm = b0 + e - NPTS; break; }
            }
            iscr[0] = levm;
        }
    }
    __syncthreads();
    const int M = iscr[0];

    // ---- integral: sum delta_i * |cdf_int_i - M| / n -------------------------
    float acc = 0.f;
#pragma unroll
    for (int e = 0; e < PER_TH; ++e) {
        int d = levs[e] - M;
        acc += dels[e] * (float)(d < 0 ? -d : d);
    }
    // block reduce
    {
        int lane = tid & 31, w = tid >> 5;
#pragma unroll
        for (int o = 16; o > 0; o >>= 1)
            acc += __shfl_down_sync(0xffffffffu, acc, o);
        if (lane == 0) fscr[w] = acc;
        __syncthreads();
        if (tid < 32) {
            float v = fscr[tid];
#pragma unroll
            for (int o = 16; o > 0; o >>= 1)
                v += __shfl_down_sync(0xffffffffu, v, o);
            if (tid == 0) g_w1[p] = v * (1.0f / (float)NPTS);
        }
    }
}

// ---------------------------------------------------------------------------
// final deterministic mean over 2000 projections
// ---------------------------------------------------------------------------
__global__ void reduce_mean_kernel(float* __restrict__ out)
{
    __shared__ float s[32];
    int tid = threadIdx.x;
    float acc = 0.f;
    for (int i = tid; i < NPROJ; i += blockDim.x) acc += g_w1[i];
#pragma unroll
    for (int o = 16; o > 0; o >>= 1)
        acc += __shfl_down_sync(0xffffffffu, acc, o);
    if ((tid & 31) == 0) s[tid >> 5] = acc;
    __syncthreads();
    if (tid < 32) {
        float v = (tid < (int)(blockDim.x >> 5)) ? s[tid] : 0.f;
#pragma unroll
        for (int o = 16; o > 0; o >>= 1)
            v += __shfl_down_sync(0xffffffffu, v, o);
        if (tid == 0) out[0] = v * (1.0f / (float)NPROJ);
    }
}

// ---------------------------------------------------------------------------
extern "C" void kernel_launch(void* const* d_in, const int* in_sizes, int n_in,
                              void* d_out, int out_size)
{
    (void)in_sizes; (void)n_in; (void)out_size;
    const float* Xs = (const float*)d_in[0];
    const float* Xt = (const float*)d_in[1];
    const float* Us = (const float*)d_in[2];

    size_t smem = (size_t)(NTOT + HBINS + 40 + 40) * sizeof(unsigned);
    cudaFuncSetAttribute(swd_proj_kernel,
                         cudaFuncAttributeMaxDynamicSharedMemorySize, (int)smem);

    swd_proj_kernel<<<NPROJ, NTHREADS, smem>>>(Xs, Xt, Us);
    reduce_mean_kernel<<<1, 256>>>((float*)d_out);
}

// round 7
// speedup vs baseline: 1.9418x; 1.9418x over previous
#include <cuda_runtime.h>
#include <math.h>

#define NPTS    4096
#define NTOT    8192
#define NPROJ   2000
#define NTHREADS 1024
#define PER_TH  8          // NTOT / NTHREADS
#define HBINS   8193       // levels -4096..4096
#define SCR_OFF 8200       // word offset of scan scratch (past hist)
#define SMEM_WORDS (SCR_OFF + 80)

// per-projection W1 results (device scratch; no allocation)
__device__ float g_w1[NPROJ];

// ---------------------------------------------------------------------------
// compare-exchange helpers
// ---------------------------------------------------------------------------
__device__ __forceinline__ void ce(unsigned& a, unsigned& b, bool up) {
    unsigned mn = min(a, b), mx = max(a, b);
    a = up ? mn : mx;
    b = up ? mx : mn;
}

// j = 4, 2, 1 within one thread's 8 elements, uniform direction (valid for k>=8)
__device__ __forceinline__ void regmerge8(unsigned r[8], bool up) {
    ce(r[0], r[4], up); ce(r[1], r[5], up); ce(r[2], r[6], up); ce(r[3], r[7], up);
    ce(r[0], r[2], up); ce(r[1], r[3], up); ce(r[4], r[6], up); ce(r[5], r[7], up);
    ce(r[0], r[1], up); ce(r[2], r[3], up); ce(r[4], r[5], up); ce(r[6], r[7], up);
}

// cross-thread pass j = 8*m via warp shuffle (m in [1,16])
__device__ __forceinline__ void shufpass(unsigned r[8], int m, bool up, int lane) {
    bool keepmin = (((lane & m) == 0) == up);
#pragma unroll
    for (int e = 0; e < 8; ++e) {
        unsigned y = __shfl_xor_sync(0xffffffffu, r[e], m);
        unsigned mn = min(r[e], y), mx = max(r[e], y);
        r[e] = keepmin ? mn : mx;
    }
}

// ---------------------------------------------------------------------------
// block-wide exclusive scan helpers (1024 threads = 32 warps)
// ---------------------------------------------------------------------------
__device__ __forceinline__ int blockScanExclInt(int v, int* scr, int tid) {
    int lane = tid & 31, w = tid >> 5;
    int inc = v;
#pragma unroll
    for (int o = 1; o < 32; o <<= 1) {
        int y = __shfl_up_sync(0xffffffffu, inc, o);
        if (lane >= o) inc += y;
    }
    if (lane == 31) scr[w] = inc;
    __syncthreads();
    if (w == 0) {
        int t = scr[lane];
#pragma unroll
        for (int o = 1; o < 32; o <<= 1) {
            int y = __shfl_up_sync(0xffffffffu, t, o);
            if (lane >= o) t += y;
        }
        scr[lane] = t;
    }
    __syncthreads();
    int base = (w == 0) ? 0 : scr[w - 1];
    return base + (inc - v);
}

__device__ __forceinline__ float blockScanExclF(float v, float* scr, int tid) {
    int lane = tid & 31, w = tid >> 5;
    float inc = v;
#pragma unroll
    for (int o = 1; o < 32; o <<= 1) {
        float y = __shfl_up_sync(0xffffffffu, inc, o);
        if (lane >= o) inc += y;
    }
    if (lane == 31) scr[w] = inc;
    __syncthreads();
    if (w == 0) {
        float t = scr[lane];
#pragma unroll
        for (int o = 1; o < 32; o <<= 1) {
            float y = __shfl_up_sync(0xffffffffu, t, o);
            if (lane >= o) t += y;
        }
        scr[lane] = t;
    }
    __syncthreads();
    float base = (w == 0) ? 0.f : scr[w - 1];
    return base + (inc - v);
}

// ---------------------------------------------------------------------------
// main kernel: one CTA per projection
// ---------------------------------------------------------------------------
__global__ __launch_bounds__(NTHREADS)
void swd_proj_kernel(const float* __restrict__ Xs,
                     const float* __restrict__ Xt,
                     const float* __restrict__ Us)
{
    extern __shared__ unsigned smem_u[];
    unsigned* keys = smem_u;                       // [0, 8192) during sort
    float*    hist = (float*)smem_u;               // [0, 8193) after sort (aliased)
    float*    fscr = (float*)&smem_u[SCR_OFF];     // 40 floats scan scratch
    int*      iscr = (int*)&smem_u[SCR_OFF + 40];  // 40 ints scan scratch

    const int tid  = threadIdx.x;
    const int lane = tid & 31;
    const int p    = blockIdx.x;
    const int base = tid * PER_TH;

    // projection basis: Us[p, d, k] row-major
    const float u00 = Us[p * 6 + 0], u01 = Us[p * 6 + 1];
    const float u10 = Us[p * 6 + 2], u11 = Us[p * 6 + 3];
    const float u20 = Us[p * 6 + 4], u21 = Us[p * 6 + 5];

    const float PIF    = 3.14159265358979323846f;
    const float INV2PI = 0.15915494309189535f;

    // ---- compute this thread's 8 packed angle keys into registers ----------
    // global elements [base, base+8): < NPTS -> Xs (tag 0), else Xt (tag 1)
    unsigned r[PER_TH];
    {
        const float* src = (base < NPTS) ? Xs : Xt;
        const int gi0    = (base < NPTS) ? base : (base - NPTS);
        const unsigned tag = (base < NPTS) ? 0u : 1u;
#pragma unroll
        for (int e = 0; e < PER_TH; ++e) {
            int i = gi0 + e;
            float x0 = src[3 * i], x1 = src[3 * i + 1], x2 = src[3 * i + 2];
            float px = x0 * u00 + x1 * u10 + x2 * u20;
            float py = x0 * u01 + x1 * u11 + x2 * u21;
            float ang = (atan2f(-py, -px) + PIF) * INV2PI;   // in [0, 1]
            r[e] = (__float_as_uint(ang) << 1) | tag;
        }
    }

    if (tid == 0) iscr[0] = -NPTS;   // fallback median level (unreachable)

    // ---- bitonic sort: register/shuffle phase (k = 2 .. 256) ---------------
    // k=2 (j=1), directions vary per element
    ce(r[0], r[1], true);  ce(r[2], r[3], false);
    ce(r[4], r[5], true);  ce(r[6], r[7], false);
    // k=4 (j=2,1)
    ce(r[0], r[2], true);  ce(r[1], r[3], true);
    ce(r[4], r[6], false); ce(r[5], r[7], false);
    ce(r[0], r[1], true);  ce(r[2], r[3], true);
    ce(r[4], r[5], false); ce(r[6], r[7], false);
    // k=8 (j=4,2,1) — uniform direction per thread
    { bool up = ((tid & 1) == 0); regmerge8(r, up); }
    // k = 16..256: shuffle passes (j=k/2..8) + register merge (j=4,2,1)
#pragma unroll
    for (int kk = 16; kk <= 256; kk <<= 1) {
        bool up = ((tid & (kk >> 3)) == 0);
#pragma unroll
        for (int m = kk >> 4; m >= 1; m >>= 1) shufpass(r, m, up, lane);
        regmerge8(r, up);
    }

    // ---- bitonic sort: global stages (k = 512 .. 8192) ----------------------
#pragma unroll
    for (int s = 0; s < 5; ++s) {
        const unsigned kk = 512u << s;
        // spill registers to smem for cross-warp passes
#pragma unroll
        for (int e = 0; e < PER_TH; ++e) keys[base + e] = r[e];
        __syncthreads();
        // smem passes: j = kk/2 down to 256
        for (unsigned j = kk >> 1; j >= 256u; j >>= 1) {
#pragma unroll
            for (int e2 = 0; e2 < (NTOT / 2) / NTHREADS; ++e2) {
                unsigned c = (unsigned)tid + (unsigned)e2 * NTHREADS;
                unsigned a = ((c & ~(j - 1u)) << 1) | (c & (j - 1u));
                unsigned b = a | j;
                unsigned x = keys[a], y = keys[b];
                bool upp = ((a & kk) == 0u);
                if ((x > y) == upp) { keys[a] = y; keys[b] = x; }
            }
            __syncthreads();
        }
        // back to registers; finish j=128..8 with shuffles, j=4,2,1 in regs
#pragma unroll
        for (int e = 0; e < PER_TH; ++e) r[e] = keys[base + e];
        bool up = ((tid & (kk >> 3)) == 0u);
        shufpass(r, 16, up, lane);
        shufpass(r, 8,  up, lane);
        shufpass(r, 4,  up, lane);
        shufpass(r, 2,  up, lane);
        shufpass(r, 1,  up, lane);
        regmerge8(r, up);
    }

    // ---- neighbor exchange: next thread's first sorted value ----------------
    __syncthreads();               // readers of keys[] done before overwrite
    keys[tid] = r[0];
    __syncthreads();
    float vnext_last = (tid == NTHREADS - 1) ? 1.0f
                       : __uint_as_float(keys[tid + 1] >> 1);
    __syncthreads();               // neighbor reads done before hist aliases keys

    // ---- zero histogram + scan of v-counts ---------------------------------
    for (int i = tid; i < HBINS; i += NTHREADS) hist[i] = 0.f;
    int vcnt = 0;
#pragma unroll
    for (int e = 0; e < PER_TH; ++e) vcnt += (int)(r[e] & 1u);
    int vexcl = blockScanExclInt(vcnt, iscr + 4, tid);
    __syncthreads();               // hist zero + scan complete

    // ---- fill level histogram weighted by deltas ----------------------------
    int   levs[PER_TH];
    float dels[PER_TH];
    {
        int vrun = vexcl;
#pragma unroll
        for (int e = 0; e < PER_TH; ++e) {
            int gi = base + e;
            vrun += (int)(r[e] & 1u);
            int lev = (gi + 1) - 2 * vrun;             // cdf_int in [-4096,4096]
            float vcur  = __uint_as_float(r[e] >> 1);
            float vnext = (e < PER_TH - 1)
                          ? __uint_as_float(r[e + 1] >> 1)
                          : vnext_last;
            float delta = vnext - vcur;
            levs[e] = lev;
            dels[e] = delta;
            atomicAdd(&hist[lev + NPTS], delta);
        }
    }
    __syncthreads();

    // ---- weighted median of levels: first bin where cum weight >= 0.5 ------
    {
        int nb = (tid == NTHREADS - 1) ? 9 : 8;
        int b0 = tid * 8;
        float sum = 0.f;
        for (int e = 0; e < nb; ++e) sum += hist[b0 + e];
        float excl = blockScanExclF(sum, fscr, tid);
        if (excl < 0.5f && excl + sum >= 0.5f) {
            float run = excl;
            int levm = b0 + nb - 1 - NPTS;
            for (int e = 0; e < nb; ++e) {
                run += hist[b0 + e];
                if (run >= 0.5f) { levm = b0 + e - NPTS; break; }
            }
            iscr[0] = levm;
        }
    }
    __syncthreads();
    const int M = iscr[0];

    // ---- integral: sum delta_i * |cdf_int_i - M| / n -------------------------
    float acc = 0.f;
#pragma unroll
    for (int e = 0; e < PER_TH; ++e) {
        int d = levs[e] - M;
        acc += dels[e] * (float)(d < 0 ? -d : d);
    }
    {
        int w = tid >> 5;
#pragma unroll
        for (int o = 16; o > 0; o >>= 1)
            acc += __shfl_down_sync(0xffffffffu, acc, o);
        if (lane == 0) fscr[w] = acc;
        __syncthreads();
        if (tid < 32) {
            float v = fscr[tid];
#pragma unroll
            for (int o = 16; o > 0; o >>= 1)
                v += __shfl_down_sync(0xffffffffu, v, o);
            if (tid == 0) g_w1[p] = v * (1.0f / (float)NPTS);
        }
    }
}

// ---------------------------------------------------------------------------
// final deterministic mean over 2000 projections
// ---------------------------------------------------------------------------
__global__ void reduce_mean_kernel(float* __restrict__ out)
{
    __shared__ float s[32];
    int tid = threadIdx.x;
    float acc = 0.f;
    for (int i = tid; i < NPROJ; i += blockDim.x) acc += g_w1[i];
#pragma unroll
    for (int o = 16; o > 0; o >>= 1)
        acc += __shfl_down_sync(0xffffffffu, acc, o);
    if ((tid & 31) == 0) s[tid >> 5] = acc;
    __syncthreads();
    if (tid < 32) {
        float v = (tid < (int)(blockDim.x >> 5)) ? s[tid] : 0.f;
#pragma unroll
        for (int o = 16; o > 0; o >>= 1)
            v += __shfl_down_sync(0xffffffffu, v, o);
        if (tid == 0) out[0] = v * (1.0f / (float)NPROJ);
    }
}

// ---------------------------------------------------------------------------
extern "C" void kernel_launch(void* const* d_in, const int* in_sizes, int n_in,
                              void* d_out, int out_size)
{
    (void)in_sizes; (void)n_in; (void)out_size;
    const float* Xs = (const float*)d_in[0];
    const float* Xt = (const float*)d_in[1];
    const float* Us = (const float*)d_in[2];

    size_t smem = (size_t)SMEM_WORDS * sizeof(unsigned);
    cudaFuncSetAttribute(swd_proj_kernel,
                         cudaFuncAttributeMaxDynamicSharedMemorySize, (int)smem);

    swd_proj_kernel<<<NPROJ, NTHREADS, smem>>>(Xs, Xt, Us);
    reduce_mean_kernel<<<1, 256>>>((float*)d_out);
}